// round 12
// baseline (speedup 1.0000x reference)
#include <cuda_runtime.h>

#define B_    64
#define CIN   512
#define COUT  512
#define HW    784      // 28*28
#define FAN   513      // CIN + 1 (rate column)
#define KSEL  256      // K = COUT * 0.5
#define RATE  0.5f

#define K1_BLOCKS 888                  // 148 SMs x 6 resident blocks
#define K1_WARPS  (K1_BLOCKS * 8)      // 7104 warps
#define NROWS     (B_ * CIN)           // 32768

// Scratch (allocation-free rule: __device__ globals)
__device__ float d_s_scr[B_ * CIN];    // per-(b,c) mean |x|
__device__ float d_g_scr[B_ * COUT];   // gate values after relu

// ---------------------------------------------------------------------------
// Kernel 1: s[b,c] = mean(|x[b,c,:,:]|). Best-measured persistent config
// (R6: 19.58us): 888 blocks, lb(256,6), grid-stride one row per warp-iter,
// plain LDG float4 body. Staggered drain -> PDL dependent overlaps cleanly.
// ---------------------------------------------------------------------------
__global__ void __launch_bounds__(256, 6) k1_absmean(const float* __restrict__ x) {
    int w    = blockIdx.x * 8 + (threadIdx.x >> 5);
    int lane = threadIdx.x & 31;
    const float4* xb = reinterpret_cast<const float4*>(x);

    for (int row = w; row < NROWS; row += K1_WARPS) {
        const float4* p = xb + (size_t)row * 196;
        float acc = 0.f;
        #pragma unroll
        for (int i = 0; i < 7; i++) {
            int idx = lane + i * 32;
            if (idx < 196) {
                float4 v = p[idx];
                acc += fabsf(v.x) + fabsf(v.y) + fabsf(v.z) + fabsf(v.w);
            }
        }
        #pragma unroll
        for (int o = 16; o; o >>= 1) acc += __shfl_xor_sync(0xffffffffu, acc, o);
        if (lane == 0) d_s_scr[row] = acc * (1.0f / (float)HW);
    }
    cudaTriggerProgrammaticLaunchCompletion();
}

// ---------------------------------------------------------------------------
// Kernel 2: g[b,c] = relu(dot(s_ext[b,:], W[c,:]) + bias[c])
// NEW TILING (the R11 experiment): grid (8,16), block = 8 batches x 32
// channels. Each W row now staged by 8 blocks (was 16) -> staged-W traffic
// during the k1-overlap window halves (16.8 -> 8.4 MB); smem 82KB -> 2
// blocks/SM in the drain window. PDL W-prologue before the grid sync.
// ---------------------------------------------------------------------------
#define B_TILE        8
#define C_TILE        32
#define W_TILE_FLOATS (C_TILE * FAN)        // 16416
#define S_STRIDE      520
#define K2_SMEM_BYTES ((W_TILE_FLOATS + B_TILE * S_STRIDE) * 4)

extern __shared__ float k2_smem[];

__global__ void k2_gate(const float* __restrict__ W, const float* __restrict__ bias) {
    float* W_sm = k2_smem;                       // [32][513] flat
    float* s_sm = k2_smem + W_TILE_FLOATS;       // [8][520]
    int tid = threadIdx.x;
    int b0  = blockIdx.x * B_TILE;
    int c0  = blockIdx.y * C_TILE;

    // ---- prologue (independent of k1): stage W tile as float4 ----
    {
        const float4* wsrc = reinterpret_cast<const float4*>(W + (size_t)c0 * FAN);
        float4* wdst = reinterpret_cast<float4*>(W_sm);
        #pragma unroll 2
        for (int i = tid; i < W_TILE_FLOATS / 4; i += 512) wdst[i] = wsrc[i];
    }

    // ---- wait for k1's stores to be visible ----
    cudaGridDependencySynchronize();

    for (int idx = tid; idx < B_TILE * FAN; idx += 512) {
        int bb = idx / FAN, k = idx - bb * FAN;
        s_sm[bb * S_STRIDE + k] = (k < CIN) ? d_s_scr[(b0 + bb) * CIN + k] : RATE;
    }
    __syncthreads();

    int warp = tid >> 5, lane = tid & 31;
    int cl = warp * 2;                       // 16 warps x 2 channels = 32
    float acc[B_TILE][2];
    #pragma unroll
    for (int bb = 0; bb < B_TILE; bb++)
        #pragma unroll
        for (int cc = 0; cc < 2; cc++) acc[bb][cc] = 0.f;

    #pragma unroll 4
    for (int k = lane; k < FAN; k += 32) {
        float wv[2], sv[B_TILE];
        #pragma unroll
        for (int cc = 0; cc < 2; cc++) wv[cc] = W_sm[(cl + cc) * FAN + k];
        #pragma unroll
        for (int bb = 0; bb < B_TILE; bb++) sv[bb] = s_sm[bb * S_STRIDE + k];
        #pragma unroll
        for (int bb = 0; bb < B_TILE; bb++)
            #pragma unroll
            for (int cc = 0; cc < 2; cc++) acc[bb][cc] += wv[cc] * sv[bb];
    }
    #pragma unroll
    for (int o = 16; o; o >>= 1)
        #pragma unroll
        for (int bb = 0; bb < B_TILE; bb++)
            #pragma unroll
            for (int cc = 0; cc < 2; cc++)
                acc[bb][cc] += __shfl_xor_sync(0xffffffffu, acc[bb][cc], o);

    if (lane == 0) {
        #pragma unroll
        for (int cc = 0; cc < 2; cc++) {
            float bv = bias[c0 + cl + cc];
            #pragma unroll
            for (int bb = 0; bb < B_TILE; bb++)
                d_g_scr[(b0 + bb) * COUT + c0 + cl + cc] = fmaxf(acc[bb][cc] + bv, 0.f);
        }
    }
    cudaTriggerProgrammaticLaunchCompletion();
}

// ---------------------------------------------------------------------------
// Kernel 3: zero the KSEL smallest per row (radix-select, 4 byte passes),
// renormalize to sum = COUT. PDL: hist-zero before the grid sync.
// (Proven R6 version, unchanged.)
// ---------------------------------------------------------------------------
__global__ void k3_select(float* __restrict__ out) {
    __shared__ unsigned hist[256];
    __shared__ unsigned sh_digit, sh_cumbefore;
    __shared__ unsigned wcnt[16];
    __shared__ float ssum[17];

    int b = blockIdx.x;
    int c = threadIdx.x;
    int warp = c >> 5, lane = c & 31;

    if (c < 256) hist[c] = 0;                // overlap-able prologue

    cudaGridDependencySynchronize();

    float gc = d_g_scr[b * COUT + c];
    unsigned key = __float_as_uint(gc);      // gc >= 0 -> monotone

    unsigned prefix = 0, mask = 0;
    unsigned target = KSEL - 1;              // remaining rank in candidate set
    unsigned countless = 0;                  // # keys strictly < tau (global)

    #pragma unroll
    for (int shift = 24; shift >= 0; shift -= 8) {
        if (shift != 24 && c < 256) hist[c] = 0;
        __syncthreads();
        bool active = ((key & mask) == prefix);
        if (active) atomicAdd(&hist[(key >> shift) & 255u], 1u);
        __syncthreads();

        if (c < 32) {   // warp0: find digit containing 'target'
            unsigned s = 0;
            #pragma unroll
            for (int k = 0; k < 8; k++) s += hist[lane * 8 + k];
            unsigned incl = s;
            #pragma unroll
            for (int o = 1; o < 32; o <<= 1) {
                unsigned t = __shfl_up_sync(0xffffffffu, incl, o);
                if (lane >= o) incl += t;
            }
            unsigned excl = incl - s;
            if (excl <= target && target < incl) {
                unsigned cum = excl;
                unsigned d = lane * 8;
                #pragma unroll
                for (int k = 0; k < 8; k++) {
                    unsigned h = hist[lane * 8 + k];
                    if (cum + h > target) { d = lane * 8 + k; break; }
                    cum += h;
                }
                sh_digit = d;
                sh_cumbefore = cum;
            }
        }
        __syncthreads();
        unsigned cb = sh_cumbefore;
        unsigned dg = sh_digit;
        target    -= cb;
        countless += cb;
        prefix |= dg << shift;
        mask   |= 0xFFu << shift;
        __syncthreads();
    }

    unsigned tau = prefix;
    unsigned E = KSEL - countless;           // # tau-equal elements to zero
    bool eq = (key == tau);

    unsigned ball = __ballot_sync(0xffffffffu, eq);
    if (lane == 0) wcnt[warp] = __popc(ball);
    __syncthreads();
    unsigned woff = 0;
    #pragma unroll
    for (int w = 0; w < 16; w++) woff += (w < warp) ? wcnt[w] : 0u;
    unsigned myoff = woff + __popc(ball & ((1u << lane) - 1u));

    bool zero = (key < tau) || (eq && myoff < E);
    float t = zero ? 0.f : gc;

    float sum = t;
    #pragma unroll
    for (int o = 16; o; o >>= 1) sum += __shfl_xor_sync(0xffffffffu, sum, o);
    if (lane == 0) ssum[warp] = sum;
    __syncthreads();
    if (c == 0) {
        float tot = 0.f;
        #pragma unroll
        for (int w = 0; w < 16; w++) tot += ssum[w];
        ssum[16] = tot;
    }
    __syncthreads();
    out[b * COUT + c] = t * ((float)COUT / ssum[16]);
}

// ---------------------------------------------------------------------------
extern "C" void kernel_launch(void* const* d_in, const int* in_sizes, int n_in,
                              void* d_out, int out_size) {
    const float* x    = (const float*)d_in[0];
    const float* W    = (const float*)d_in[1];
    const float* bias = (const float*)d_in[2];
    float* out = (float*)d_out;

    cudaFuncSetAttribute(k2_gate, cudaFuncAttributeMaxDynamicSharedMemorySize,
                         K2_SMEM_BYTES);

    k1_absmean<<<K1_BLOCKS, 256>>>(x);

    // k2 with Programmatic Dependent Launch (launches into k1's drain window)
    {
        cudaLaunchConfig_t cfg = {};
        cfg.gridDim  = dim3(8, 16);
        cfg.blockDim = dim3(512);
        cfg.dynamicSmemBytes = K2_SMEM_BYTES;
        cfg.stream = 0;
        cudaLaunchAttribute at[1];
        at[0].id = cudaLaunchAttributeProgrammaticStreamSerialization;
        at[0].val.programmaticStreamSerializationAllowed = 1;
        cfg.attrs = at;
        cfg.numAttrs = 1;
        cudaLaunchKernelEx(&cfg, k2_gate, W, bias);
    }

    // k3 with PDL: dispatch overlaps k2's tail.
    {
        cudaLaunchConfig_t cfg = {};
        cfg.gridDim  = dim3(B_);
        cfg.blockDim = dim3(512);
        cfg.dynamicSmemBytes = 0;
        cfg.stream = 0;
        cudaLaunchAttribute at[1];
        at[0].id = cudaLaunchAttributeProgrammaticStreamSerialization;
        at[0].val.programmaticStreamSerializationAllowed = 1;
        cfg.attrs = at;
        cfg.numAttrs = 1;
        cudaLaunchKernelEx(&cfg, k3_select, out);
    }
}

// round 13
// speedup vs baseline: 1.0976x; 1.0976x over previous
#include <cuda_runtime.h>

#define B_    64
#define CIN   512
#define COUT  512
#define HW    784      // 28*28
#define FAN   513      // CIN + 1 (rate column)
#define KSEL  256      // K = COUT * 0.5
#define RATE  0.5f

#define K1_BLOCKS 888                  // 148 SMs x 6 resident blocks
#define K1_WARPS  (K1_BLOCKS * 8)      // 7104 warps
#define NROWS     (B_ * CIN)           // 32768

// Scratch (allocation-free rule: __device__ globals)
__device__ float d_s_scr[B_ * CIN];    // per-(b,c) mean |x|
__device__ float d_g_scr[B_ * COUT];   // gate values after relu

// ---------------------------------------------------------------------------
// Kernel 1: s[b,c] = mean(|x[b,c,:,:]|). Best-measured persistent config
// (R6/R11: 19.52-19.58us): 888 blocks, lb(256,6), grid-stride one row per
// warp-iter, plain LDG float4 body. Staggered drain -> PDL overlap.
// ---------------------------------------------------------------------------
__global__ void __launch_bounds__(256, 6) k1_absmean(const float* __restrict__ x) {
    int w    = blockIdx.x * 8 + (threadIdx.x >> 5);
    int lane = threadIdx.x & 31;
    const float4* xb = reinterpret_cast<const float4*>(x);

    for (int row = w; row < NROWS; row += K1_WARPS) {
        const float4* p = xb + (size_t)row * 196;
        float acc = 0.f;
        #pragma unroll
        for (int i = 0; i < 7; i++) {
            int idx = lane + i * 32;
            if (idx < 196) {
                float4 v = p[idx];
                acc += fabsf(v.x) + fabsf(v.y) + fabsf(v.z) + fabsf(v.w);
            }
        }
        #pragma unroll
        for (int o = 16; o; o >>= 1) acc += __shfl_xor_sync(0xffffffffu, acc, o);
        if (lane == 0) d_s_scr[row] = acc * (1.0f / (float)HW);
    }
    cudaTriggerProgrammaticLaunchCompletion();
}

// ---------------------------------------------------------------------------
// Kernel 2: g[b,c] = relu(dot(s_ext[b,:], W[c,:]) + bias[c])
// R6 tiling (measured best): grid (16,8), block = 4 batches x 64 channels.
// PDL prologue stages the W tile AND the bias tile (neither depends on k1)
// before the grid-dependency sync; post-sync path reads only smem.
// ---------------------------------------------------------------------------
#define W_TILE_FLOATS (64 * FAN)            // 32832
#define S_STRIDE      520
#define K2_SMEM_FLTS  (W_TILE_FLOATS + 4 * S_STRIDE + 64)
#define K2_SMEM_BYTES (K2_SMEM_FLTS * 4)

extern __shared__ float k2_smem[];

__global__ void k2_gate(const float* __restrict__ W, const float* __restrict__ bias) {
    float* W_sm = k2_smem;                            // [64][513] flat
    float* s_sm = k2_smem + W_TILE_FLOATS;            // [4][520]
    float* b_sm = s_sm + 4 * S_STRIDE;                // [64]
    int tid = threadIdx.x;
    int b0  = blockIdx.x * 4;
    int c0  = blockIdx.y * 64;

    // ---- prologue (independent of k1): stage W tile + bias tile ----
    {
        const float4* wsrc = reinterpret_cast<const float4*>(W + (size_t)c0 * FAN);
        float4* wdst = reinterpret_cast<float4*>(W_sm);
        #pragma unroll 4
        for (int i = tid; i < W_TILE_FLOATS / 4; i += 512) wdst[i] = wsrc[i];
        if (tid < 64) b_sm[tid] = bias[c0 + tid];
    }

    // ---- wait for k1's stores to be visible ----
    cudaGridDependencySynchronize();

    for (int idx = tid; idx < 4 * FAN; idx += 512) {
        int bb = idx / FAN, k = idx - bb * FAN;
        s_sm[bb * S_STRIDE + k] = (k < CIN) ? d_s_scr[(b0 + bb) * CIN + k] : RATE;
    }
    __syncthreads();

    int warp = tid >> 5, lane = tid & 31;
    int cl = warp * 4;                       // 16 warps x 4 channels = 64
    float acc[4][4];
    #pragma unroll
    for (int bb = 0; bb < 4; bb++)
        #pragma unroll
        for (int cc = 0; cc < 4; cc++) acc[bb][cc] = 0.f;

    #pragma unroll 4
    for (int k = lane; k < FAN; k += 32) {
        float wv[4], sv[4];
        #pragma unroll
        for (int cc = 0; cc < 4; cc++) wv[cc] = W_sm[(cl + cc) * FAN + k];
        #pragma unroll
        for (int bb = 0; bb < 4; bb++) sv[bb] = s_sm[bb * S_STRIDE + k];
        #pragma unroll
        for (int bb = 0; bb < 4; bb++)
            #pragma unroll
            for (int cc = 0; cc < 4; cc++) acc[bb][cc] += wv[cc] * sv[bb];
    }
    #pragma unroll
    for (int o = 16; o; o >>= 1)
        #pragma unroll
        for (int bb = 0; bb < 4; bb++)
            #pragma unroll
            for (int cc = 0; cc < 4; cc++)
                acc[bb][cc] += __shfl_xor_sync(0xffffffffu, acc[bb][cc], o);

    if (lane == 0) {
        #pragma unroll
        for (int cc = 0; cc < 4; cc++) {
            float bv = b_sm[cl + cc];
            #pragma unroll
            for (int bb = 0; bb < 4; bb++)
                d_g_scr[(b0 + bb) * COUT + c0 + cl + cc] = fmaxf(acc[bb][cc] + bv, 0.f);
        }
    }
    cudaTriggerProgrammaticLaunchCompletion();
}

// ---------------------------------------------------------------------------
// Kernel 3: zero the KSEL smallest per row (radix-select, 4 byte passes),
// renormalize to sum = COUT. PDL: hist-zero before the grid sync.
// Trim: final row-sum drops one __syncthreads + serial thread-0 chain
// (every thread sums the 16 warp partials itself).
// ---------------------------------------------------------------------------
__global__ void k3_select(float* __restrict__ out) {
    __shared__ unsigned hist[256];
    __shared__ unsigned sh_digit, sh_cumbefore;
    __shared__ unsigned wcnt[16];
    __shared__ float ssum[16];

    int b = blockIdx.x;
    int c = threadIdx.x;
    int warp = c >> 5, lane = c & 31;

    if (c < 256) hist[c] = 0;                // overlap-able prologue

    cudaGridDependencySynchronize();

    float gc = d_g_scr[b * COUT + c];
    unsigned key = __float_as_uint(gc);      // gc >= 0 -> monotone

    unsigned prefix = 0, mask = 0;
    unsigned target = KSEL - 1;              // remaining rank in candidate set
    unsigned countless = 0;                  // # keys strictly < tau (global)

    #pragma unroll
    for (int shift = 24; shift >= 0; shift -= 8) {
        if (shift != 24 && c < 256) hist[c] = 0;
        __syncthreads();
        bool active = ((key & mask) == prefix);
        if (active) atomicAdd(&hist[(key >> shift) & 255u], 1u);
        __syncthreads();

        if (c < 32) {   // warp0: find digit containing 'target'
            unsigned s = 0;
            #pragma unroll
            for (int k = 0; k < 8; k++) s += hist[lane * 8 + k];
            unsigned incl = s;
            #pragma unroll
            for (int o = 1; o < 32; o <<= 1) {
                unsigned t = __shfl_up_sync(0xffffffffu, incl, o);
                if (lane >= o) incl += t;
            }
            unsigned excl = incl - s;
            if (excl <= target && target < incl) {
                unsigned cum = excl;
                unsigned d = lane * 8;
                #pragma unroll
                for (int k = 0; k < 8; k++) {
                    unsigned h = hist[lane * 8 + k];
                    if (cum + h > target) { d = lane * 8 + k; break; }
                    cum += h;
                }
                sh_digit = d;
                sh_cumbefore = cum;
            }
        }
        __syncthreads();
        unsigned cb = sh_cumbefore;
        unsigned dg = sh_digit;
        target    -= cb;
        countless += cb;
        prefix |= dg << shift;
        mask   |= 0xFFu << shift;
        __syncthreads();
    }

    unsigned tau = prefix;
    unsigned E = KSEL - countless;           // # tau-equal elements to zero
    bool eq = (key == tau);

    unsigned ball = __ballot_sync(0xffffffffu, eq);
    if (lane == 0) wcnt[warp] = __popc(ball);
    __syncthreads();
    unsigned woff = 0;
    #pragma unroll
    for (int w = 0; w < 16; w++) woff += (w < warp) ? wcnt[w] : 0u;
    unsigned myoff = woff + __popc(ball & ((1u << lane) - 1u));

    bool zero = (key < tau) || (eq && myoff < E);
    float t = zero ? 0.f : gc;

    float sum = t;
    #pragma unroll
    for (int o = 16; o; o >>= 1) sum += __shfl_xor_sync(0xffffffffu, sum, o);
    if (lane == 0) ssum[warp] = sum;
    __syncthreads();
    float tot = 0.f;
    #pragma unroll
    for (int w = 0; w < 16; w++) tot += ssum[w];   // all threads, no extra sync
    out[b * COUT + c] = t * ((float)COUT / tot);
}

// ---------------------------------------------------------------------------
extern "C" void kernel_launch(void* const* d_in, const int* in_sizes, int n_in,
                              void* d_out, int out_size) {
    const float* x    = (const float*)d_in[0];
    const float* W    = (const float*)d_in[1];
    const float* bias = (const float*)d_in[2];
    float* out = (float*)d_out;

    cudaFuncSetAttribute(k2_gate, cudaFuncAttributeMaxDynamicSharedMemorySize,
                         K2_SMEM_BYTES);

    k1_absmean<<<K1_BLOCKS, 256>>>(x);

    // k2 with Programmatic Dependent Launch (launches into k1's drain window)
    {
        cudaLaunchConfig_t cfg = {};
        cfg.gridDim  = dim3(16, 8);
        cfg.blockDim = dim3(512);
        cfg.dynamicSmemBytes = K2_SMEM_BYTES;
        cfg.stream = 0;
        cudaLaunchAttribute at[1];
        at[0].id = cudaLaunchAttributeProgrammaticStreamSerialization;
        at[0].val.programmaticStreamSerializationAllowed = 1;
        cfg.attrs = at;
        cfg.numAttrs = 1;
        cudaLaunchKernelEx(&cfg, k2_gate, W, bias);
    }

    // k3 with PDL: dispatch overlaps k2's tail.
    {
        cudaLaunchConfig_t cfg = {};
        cfg.gridDim  = dim3(B_);
        cfg.blockDim = dim3(512);
        cfg.dynamicSmemBytes = 0;
        cfg.stream = 0;
        cudaLaunchAttribute at[1];
        at[0].id = cudaLaunchAttributeProgrammaticStreamSerialization;
        at[0].val.programmaticStreamSerializationAllowed = 1;
        cfg.attrs = at;
        cfg.numAttrs = 1;
        cudaLaunchKernelEx(&cfg, k3_select, out);
    }
}